// round 5
// baseline (speedup 1.0000x reference)
#include <cuda_runtime.h>

// Problem constants
#define BATCH 2
#define DIM   192
#define PLANE (DIM*DIM)           // 36864
#define VOL   (DIM*DIM*DIM)       // 7077888
#define NVOX  (BATCH*VOL)         // 14155776
#define RW    4                   // window radius (WIN=9)
#define INV729 (1.0f/729.0f)
#define EPSV  1e-5f
#define CHUNK 48                  // y/z chunk per block (192/48 = 4 chunks)
#define NCHUNK (DIM/CHUNK)

// Scratch: two sets of five f32 fields (ping-pong across separable passes).
// __device__ globals are the allocation-guard-safe way to get scratch.
__device__ float g_A[5][NVOX];    // after x-pass
__device__ float g_B[5][NVOX];    // after y-pass
__device__ float g_part[BATCH*DIM*NCHUNK];  // per-block partial ncc sums (1536)

// ---------------------------------------------------------------------------
// Pass 1: x-direction 9-tap box sums of {I, J, I^2, J^2, I*J}.
// One block per row (b,z,y); 192 threads = one thread per x.
// ---------------------------------------------------------------------------
__global__ void k_pass1(const float* __restrict__ I, const float* __restrict__ J) {
    __shared__ float sI[DIM];
    __shared__ float sJ[DIM];
    const int  x    = threadIdx.x;
    const int  base = blockIdx.x * DIM;   // row start (blockIdx.x < 73728)

    const float iv = I[base + x];
    const float jv = J[base + x];
    sI[x] = iv;
    sJ[x] = jv;
    __syncthreads();

    float a = 0.f, b = 0.f, c = 0.f, d = 0.f, e = 0.f;
#pragma unroll
    for (int k = -RW; k <= RW; k++) {
        const int xx = x + k;
        if (xx >= 0 && xx < DIM) {
            const float u = sI[xx];
            const float v = sJ[xx];
            a += u;  b += v;  c += u * u;  d += v * v;  e += u * v;
        }
    }
    const int idx = base + x;
    g_A[0][idx] = a;
    g_A[1][idx] = b;
    g_A[2][idx] = c;
    g_A[3][idx] = d;
    g_A[4][idx] = e;
}

// ---------------------------------------------------------------------------
// Pass 2: y-direction 9-tap box sums via register rolling sums.
// grid = (BATCH*DIM [b,z planes], NCHUNK [y chunks]); block = 192 threads (x).
// The subtract-tap re-read (y-4) was read 9 iterations ago -> L1 hit
// (per-block window working set: 9 rows x 5 fields x 768 B = ~35 KB).
// ---------------------------------------------------------------------------
__global__ void k_pass2() {
    const int bz   = blockIdx.x;              // b*DIM + z
    const int y0   = blockIdx.y * CHUNK;
    const int x    = threadIdx.x;
    const int base = bz * PLANE + x;          // (b,z,0,x)

    const float* __restrict__ A0 = g_A[0];
    const float* __restrict__ A1 = g_A[1];
    const float* __restrict__ A2 = g_A[2];
    const float* __restrict__ A3 = g_A[3];
    const float* __restrict__ A4 = g_A[4];

    float s0 = 0.f, s1 = 0.f, s2 = 0.f, s3 = 0.f, s4 = 0.f;
#pragma unroll
    for (int k = -RW; k <= RW; k++) {
        const int yy = y0 + k;
        if (yy >= 0 && yy < DIM) {
            const int id = base + yy * DIM;
            s0 += A0[id]; s1 += A1[id]; s2 += A2[id]; s3 += A3[id]; s4 += A4[id];
        }
    }

    for (int y = y0; y < y0 + CHUNK; y++) {
        const int id = base + y * DIM;
        g_B[0][id] = s0;
        g_B[1][id] = s1;
        g_B[2][id] = s2;
        g_B[3][id] = s3;
        g_B[4][id] = s4;
        const int ya = y + RW + 1;   // entering row
        const int yr = y - RW;       // leaving row
        if (ya < DIM) {
            const int ida = base + ya * DIM;
            s0 += A0[ida]; s1 += A1[ida]; s2 += A2[ida]; s3 += A3[ida]; s4 += A4[ida];
        }
        if (yr >= 0) {
            const int idr = base + yr * DIM;
            s0 -= A0[idr]; s1 -= A1[idr]; s2 -= A2[idr]; s3 -= A3[idr]; s4 -= A4[idr];
        }
    }
}

// ---------------------------------------------------------------------------
// Pass 3: z-direction rolling sums + NCC + per-block reduction.
// grid = (BATCH*DIM [b,y lines], NCHUNK [z chunks]); block = 192 threads (x).
// Subtract-tap (z-4) hits L2: full 9-plane x 5-field window = ~13 MB << L2.
// Writes a deterministic per-block partial (no float atomics -> identical
// result on every graph replay).
// ---------------------------------------------------------------------------
__global__ void k_pass3() {
    const int by   = blockIdx.x;              // b*DIM + y
    const int b    = by / DIM;
    const int y    = by % DIM;
    const int z0   = blockIdx.y * CHUNK;
    const int x    = threadIdx.x;
    const int base = b * VOL + y * DIM + x;   // (b,0,y,x)

    const float* __restrict__ B0 = g_B[0];
    const float* __restrict__ B1 = g_B[1];
    const float* __restrict__ B2 = g_B[2];
    const float* __restrict__ B3 = g_B[3];
    const float* __restrict__ B4 = g_B[4];

    float s0 = 0.f, s1 = 0.f, s2 = 0.f, s3 = 0.f, s4 = 0.f;
#pragma unroll
    for (int k = -RW; k <= RW; k++) {
        const int zz = z0 + k;
        if (zz >= 0 && zz < DIM) {
            const int id = base + zz * PLANE;
            s0 += B0[id]; s1 += B1[id]; s2 += B2[id]; s3 += B3[id]; s4 += B4[id];
        }
    }

    float acc = 0.f;
    for (int z = z0; z < z0 + CHUNK; z++) {
        const float uI = s0 * INV729;
        const float uJ = s1 * INV729;
        const float I2 = s2 * INV729 - uI * uI;
        const float J2 = s3 * INV729 - uJ * uJ;
        const float IJ = s4 * INV729 - uI * uJ;
        acc += (IJ * IJ) / (I2 * J2 + EPSV);

        const int za = z + RW + 1;
        const int zr = z - RW;
        if (za < DIM) {
            const int ida = base + za * PLANE;
            s0 += B0[ida]; s1 += B1[ida]; s2 += B2[ida]; s3 += B3[ida]; s4 += B4[ida];
        }
        if (zr >= 0) {
            const int idr = base + zr * PLANE;
            s0 -= B0[idr]; s1 -= B1[idr]; s2 -= B2[idr]; s3 -= B3[idr]; s4 -= B4[idr];
        }
    }

    // Block tree-reduce 192 partials (192 = 3 * 2^6).
    __shared__ float red[DIM];
    red[x] = acc;
    __syncthreads();
#pragma unroll
    for (int s = 96; s >= 3; s >>= 1) {
        if (x < s) red[x] += red[x + s];
        __syncthreads();
    }
    if (x == 0) {
        g_part[blockIdx.y * (BATCH * DIM) + blockIdx.x] = red[0] + red[1] + red[2];
    }
}

// ---------------------------------------------------------------------------
// Final: deterministic fixed-order sum of 1536 partials -> -mean(ncc).
// ---------------------------------------------------------------------------
__global__ void k_final(float* __restrict__ out) {
    __shared__ float red[256];
    const int t = threadIdx.x;
    float acc = 0.f;
    for (int i = t; i < BATCH * DIM * NCHUNK; i += 256) acc += g_part[i];
    red[t] = acc;
    __syncthreads();
#pragma unroll
    for (int s = 128; s > 0; s >>= 1) {
        if (t < s) red[t] += red[t + s];
        __syncthreads();
    }
    if (t == 0) out[0] = -red[0] * (1.0f / (float)NVOX);
}

extern "C" void kernel_launch(void* const* d_in, const int* in_sizes, int n_in,
                              void* d_out, int out_size) {
    const float* y_pred = (const float*)d_in[0];
    const float* y_true = (const float*)d_in[1];
    float* out = (float*)d_out;

    k_pass1<<<BATCH * DIM * DIM, DIM>>>(y_pred, y_true);
    k_pass2<<<dim3(BATCH * DIM, NCHUNK), DIM>>>();
    k_pass3<<<dim3(BATCH * DIM, NCHUNK), DIM>>>();
    k_final<<<1, 256>>>(out);
}

// round 8
// speedup vs baseline: 1.7245x; 1.7245x over previous
#include <cuda_runtime.h>

// Problem constants
#define BATCH 2
#define DIM   192
#define PLANE (DIM*DIM)           // 36864
#define VOL   (DIM*DIM*DIM)       // 7077888
#define NVOX  (BATCH*VOL)         // 14155776
#define RW    4                   // window radius (WIN=9)
#define WIN   9
#define INV729 (1.0f/729.0f)
#define EPSV  1e-5f
#define CHUNK 48                  // y/z chunk per block (192/48 = 4 chunks)
#define NCHUNK (DIM/CHUNK)

// Scratch: single set of five f32 fields (after fused x+y pass).
// __device__ globals are the allocation-guard-safe way to get scratch.
__device__ float g_B[5][NVOX];
__device__ float g_part[BATCH*DIM*NCHUNK];  // per-block partial ncc sums (1536)

// ---------------------------------------------------------------------------
// Compute one x-boxed row: load I,J row into padded smem, 9-tap box sums of
// {I, J, I^2, J^2, I*J}. Pads are pre-zeroed, so taps are branch-free.
// ---------------------------------------------------------------------------
__device__ __forceinline__ void xbox_row(
    const float* __restrict__ I, const float* __restrict__ J,
    int gbase, int x, float* sI, float* sJ, float a[5])
{
    __syncthreads();                   // prior readers of sI/sJ done
    sI[RW + x] = I[gbase + x];
    sJ[RW + x] = J[gbase + x];
    __syncthreads();
    float a0 = 0.f, a1 = 0.f, a2 = 0.f, a3 = 0.f, a4 = 0.f;
#pragma unroll
    for (int k = 0; k < WIN; k++) {
        const float u = sI[x + k];
        const float v = sJ[x + k];
        a0 += u; a1 += v; a2 += u*u; a3 += v*v; a4 += u*v;
    }
    a[0]=a0; a[1]=a1; a[2]=a2; a[3]=a3; a[4]=a4;
}

// ---------------------------------------------------------------------------
// Fused pass 1+2: x-direction box (via smem row) + y-direction box (register
// rolling sums, smem ring of last 9 x-boxed rows so the subtract-tap never
// re-reads global). grid = (BATCH*DIM [b,z planes], NCHUNK [y chunks]),
// block = 192 threads (one per x). Each I/J element read ~1.17x (chunk halo),
// each g_B element written once.
// ---------------------------------------------------------------------------
__global__ __launch_bounds__(DIM) void k_pass12(
    const float* __restrict__ I, const float* __restrict__ J)
{
    __shared__ float ring[WIN][5][DIM];     // 34.6 KB: last 9 x-boxed rows
    __shared__ float sI[DIM + 2*RW];
    __shared__ float sJ[DIM + 2*RW];

    const int bz = blockIdx.x;              // b*DIM + z
    const int y0 = blockIdx.y * CHUNK;
    const int x  = threadIdx.x;
    const int pb = bz * PLANE;              // (b,z,0,0)

    // zero pads once (covered by the first xbox_row's leading sync)
    if (x < RW) {
        sI[x] = 0.f;          sJ[x] = 0.f;
        sI[RW + DIM + x] = 0.f; sJ[RW + DIM + x] = 0.f;
    }

    float s0=0.f, s1=0.f, s2=0.f, s3=0.f, s4=0.f;
    float a[5];

    // Prologue: rows [y0-4, y0+4] (clamped low; high end always < DIM)
    const int rlo = (y0 - RW < 0) ? 0 : (y0 - RW);
    for (int r = rlo; r <= y0 + RW; r++) {
        xbox_row(I, J, pb + r*DIM, x, sI, sJ, a);
        const int sl = r % WIN;
        ring[sl][0][x]=a[0]; ring[sl][1][x]=a[1]; ring[sl][2][x]=a[2];
        ring[sl][3][x]=a[3]; ring[sl][4][x]=a[4];
        s0+=a[0]; s1+=a[1]; s2+=a[2]; s3+=a[3]; s4+=a[4];
    }

    for (int y = y0; ; y++) {
        const int id = pb + y*DIM + x;
        g_B[0][id]=s0; g_B[1][id]=s1; g_B[2][id]=s2; g_B[3][id]=s3; g_B[4][id]=s4;
        if (y == y0 + CHUNK - 1) break;

        const int rs = y - RW;              // leaving row (from smem ring)
        if (rs >= 0) {
            const int sl = rs % WIN;
            s0-=ring[sl][0][x]; s1-=ring[sl][1][x]; s2-=ring[sl][2][x];
            s3-=ring[sl][3][x]; s4-=ring[sl][4][x];
        }
        const int ra = y + RW + 1;          // entering row (same ring slot: rs+9)
        if (ra < DIM) {
            xbox_row(I, J, pb + ra*DIM, x, sI, sJ, a);
            const int sl = ra % WIN;
            ring[sl][0][x]=a[0]; ring[sl][1][x]=a[1]; ring[sl][2][x]=a[2];
            ring[sl][3][x]=a[3]; ring[sl][4][x]=a[4];
            s0+=a[0]; s1+=a[1]; s2+=a[2]; s3+=a[3]; s4+=a[4];
        }
    }
}

// ---------------------------------------------------------------------------
// Pass 3: z-direction rolling sums + NCC + per-block reduction.
// grid = (BATCH*DIM [b,y lines], NCHUNK [z chunks]); block = 192 threads (x).
// Smem ring holds the last 9 z-rows: each g_B element is loaded from global
// exactly once (subtract-tap served from smem). Deterministic per-block
// partial -> identical result on every graph replay.
// ---------------------------------------------------------------------------
__global__ __launch_bounds__(DIM) void k_pass3() {
    __shared__ float ring[WIN][5][DIM];     // 34.6 KB
    __shared__ float red[DIM];

    const int by = blockIdx.x;              // b*DIM + y
    const int b  = by / DIM;
    const int y  = by % DIM;
    const int z0 = blockIdx.y * CHUNK;
    const int x  = threadIdx.x;
    const int base = b * VOL + y * DIM + x; // (b,0,y,x)

    const float* __restrict__ B0 = g_B[0];
    const float* __restrict__ B1 = g_B[1];
    const float* __restrict__ B2 = g_B[2];
    const float* __restrict__ B3 = g_B[3];
    const float* __restrict__ B4 = g_B[4];

    float s0=0.f, s1=0.f, s2=0.f, s3=0.f, s4=0.f;

    const int rlo = (z0 - RW < 0) ? 0 : (z0 - RW);
    for (int r = rlo; r <= z0 + RW; r++) {
        const int id = base + r * PLANE;
        const float a0=B0[id], a1=B1[id], a2=B2[id], a3=B3[id], a4=B4[id];
        const int sl = r % WIN;
        ring[sl][0][x]=a0; ring[sl][1][x]=a1; ring[sl][2][x]=a2;
        ring[sl][3][x]=a3; ring[sl][4][x]=a4;
        s0+=a0; s1+=a1; s2+=a2; s3+=a3; s4+=a4;
    }

    float acc = 0.f;
    for (int z = z0; ; z++) {
        const float uI = s0 * INV729;
        const float uJ = s1 * INV729;
        const float I2 = s2 * INV729 - uI * uI;
        const float J2 = s3 * INV729 - uJ * uJ;
        const float IJ = s4 * INV729 - uI * uJ;
        acc += (IJ * IJ) / (I2 * J2 + EPSV);
        if (z == z0 + CHUNK - 1) break;

        const int rs = z - RW;
        if (rs >= 0) {
            const int sl = rs % WIN;
            s0-=ring[sl][0][x]; s1-=ring[sl][1][x]; s2-=ring[sl][2][x];
            s3-=ring[sl][3][x]; s4-=ring[sl][4][x];
        }
        const int ra = z + RW + 1;
        if (ra < DIM) {
            const int id = base + ra * PLANE;
            const float a0=B0[id], a1=B1[id], a2=B2[id], a3=B3[id], a4=B4[id];
            const int sl = ra % WIN;
            ring[sl][0][x]=a0; ring[sl][1][x]=a1; ring[sl][2][x]=a2;
            ring[sl][3][x]=a3; ring[sl][4][x]=a4;
            s0+=a0; s1+=a1; s2+=a2; s3+=a3; s4+=a4;
        }
    }

    // Block tree-reduce 192 partials (192 = 3 * 2^6).
    red[x] = acc;
    __syncthreads();
#pragma unroll
    for (int s = 96; s >= 3; s >>= 1) {
        if (x < s) red[x] += red[x + s];
        __syncthreads();
    }
    if (x == 0) {
        g_part[blockIdx.y * (BATCH * DIM) + blockIdx.x] = red[0] + red[1] + red[2];
    }
}

// ---------------------------------------------------------------------------
// Final: deterministic fixed-order sum of 1536 partials -> -mean(ncc).
// ---------------------------------------------------------------------------
__global__ void k_final(float* __restrict__ out) {
    __shared__ float red[256];
    const int t = threadIdx.x;
    float acc = 0.f;
    for (int i = t; i < BATCH * DIM * NCHUNK; i += 256) acc += g_part[i];
    red[t] = acc;
    __syncthreads();
#pragma unroll
    for (int s = 128; s > 0; s >>= 1) {
        if (t < s) red[t] += red[t + s];
        __syncthreads();
    }
    if (t == 0) out[0] = -red[0] * (1.0f / (float)NVOX);
}

extern "C" void kernel_launch(void* const* d_in, const int* in_sizes, int n_in,
                              void* d_out, int out_size) {
    const float* y_pred = (const float*)d_in[0];
    const float* y_true = (const float*)d_in[1];
    float* out = (float*)d_out;

    k_pass12<<<dim3(BATCH * DIM, NCHUNK), DIM>>>(y_pred, y_true);
    k_pass3 <<<dim3(BATCH * DIM, NCHUNK), DIM>>>();
    k_final <<<1, 256>>>(out);
}

// round 9
// speedup vs baseline: 2.1502x; 1.2468x over previous
#include <cuda_runtime.h>
#include <cuda_fp16.h>

// Problem constants
#define BATCH 2
#define DIM   192
#define PLANE (DIM*DIM)           // 36864
#define VOL   (DIM*DIM*DIM)       // 7077888
#define NVOX  (BATCH*VOL)         // 14155776
#define RW    4                   // window radius (WIN=9)
#define WIN   9
#define INV729 (1.0f/729.0f)
#define EPSV  1e-5f
#define CHUNK 48                  // y/z chunk per block (192/48 = 4 chunks)
#define NCHUNK (DIM/CHUNK)

// Intermediate (after fused x+y pass): five pooled-sum fields packed in half.
// 10 B/vox instead of 20 -> halves pass3 DRAM read + pass12 DRAM write.
__device__ unsigned gB01[NVOX];   // half2(s0, s1)  = (SumI, SumJ)
__device__ unsigned gB23[NVOX];   // half2(s2, s3)  = (SumI2, SumJ2)
__device__ __half   gB4 [NVOX];   // half(s4)       = SumIJ
__device__ float g_part[BATCH*DIM*NCHUNK];  // per-block partial ncc sums (1536)

__device__ __forceinline__ unsigned pk2(float a, float b) {
    __half2 h = __floats2half2_rn(a, b);
    return *reinterpret_cast<unsigned*>(&h);
}
__device__ __forceinline__ float2 up2(unsigned u) {
    __half2 h = *reinterpret_cast<__half2*>(&u);
    return __half22float2(h);
}

// ---------------------------------------------------------------------------
// Fused pass 1+2: x-box (smem row, 9 taps on I,J with products in registers)
// + y-box (register rolling sums; smem ring of the last 9 x-boxed rows, packed
// half). Rounding discipline: each row's contribution is rounded to half FIRST
// and the rounded value is both added to the rolling sum and stored in the
// ring -> subtract is exact, no drift.
// Double-buffered input rows -> ONE __syncthreads per row (barrier of row r-1
// separates reads of buffer p at row r-2 from writes of buffer p at row r).
// Smem ~24 KB -> 10 resident blocks (warp-capped), occ ~80%.
// grid = (BATCH*DIM [b,z planes], NCHUNK [y chunks]); block = 192 (x).
// ---------------------------------------------------------------------------
__global__ __launch_bounds__(DIM) void k_pass12(
    const float* __restrict__ I, const float* __restrict__ J)
{
    __shared__ unsigned r01[WIN][DIM];        // 6.9 KB
    __shared__ unsigned r23[WIN][DIM];        // 6.9 KB
    __shared__ __half   r4 [WIN][DIM];        // 3.5 KB
    __shared__ float    sbuf[2][2][DIM + 2*RW]; // [parity][I/J][x]  6.4 KB

    const int bz = blockIdx.x;                // b*DIM + z
    const int y0 = blockIdx.y * CHUNK;
    const int x  = threadIdx.x;
    const int pb = bz * PLANE;

    if (x < RW) {                             // zero pads (both parities)
#pragma unroll
        for (int p = 0; p < 2; p++) {
            sbuf[p][0][x] = 0.f;            sbuf[p][1][x] = 0.f;
            sbuf[p][0][RW + DIM + x] = 0.f; sbuf[p][1][RW + DIM + x] = 0.f;
        }
    }

    float s0 = 0.f, s1 = 0.f, s2 = 0.f, s3 = 0.f, s4 = 0.f;

    // Process one input row r: x-box it, round to half, push to ring, add to s.
    auto do_row = [&](int r) {
        float* sI = sbuf[r & 1][0];
        float* sJ = sbuf[r & 1][1];
        sI[RW + x] = I[pb + r * DIM + x];
        sJ[RW + x] = J[pb + r * DIM + x];
        __syncthreads();
        float a0 = 0.f, a1 = 0.f, a2 = 0.f, a3 = 0.f, a4 = 0.f;
#pragma unroll
        for (int k = 0; k < WIN; k++) {
            const float u = sI[x + k];
            const float v = sJ[x + k];
            a0 += u; a1 += v; a2 += u*u; a3 += v*v; a4 += u*v;
        }
        const unsigned u01 = pk2(a0, a1);
        const unsigned u23 = pk2(a2, a3);
        const __half   h4  = __float2half_rn(a4);
        const int sl = r % WIN;
        r01[sl][x] = u01; r23[sl][x] = u23; r4[sl][x] = h4;
        const float2 f01 = up2(u01);
        const float2 f23 = up2(u23);
        s0 += f01.x; s1 += f01.y; s2 += f23.x; s3 += f23.y;
        s4 += __half2float(h4);
    };

    // Prologue: rows [max(0, y0-4), y0+4]
    const int rlo = (y0 - RW < 0) ? 0 : (y0 - RW);
    for (int r = rlo; r <= y0 + RW; r++) do_row(r);

    for (int y = y0; ; y++) {
        const int id = pb + y * DIM + x;
        gB01[id] = pk2(s0, s1);
        gB23[id] = pk2(s2, s3);
        gB4 [id] = __float2half_rn(s4);
        if (y == y0 + CHUNK - 1) break;

        const int rs = y - RW;                // leaving row (exact subtract)
        if (rs >= 0) {
            const int sl = rs % WIN;
            const float2 f01 = up2(r01[sl][x]);
            const float2 f23 = up2(r23[sl][x]);
            s0 -= f01.x; s1 -= f01.y; s2 -= f23.x; s3 -= f23.y;
            s4 -= __half2float(r4[sl][x]);
        }
        const int ra = y + RW + 1;            // entering row
        if (ra < DIM) do_row(ra);
    }
}

// ---------------------------------------------------------------------------
// Pass 3: z-direction rolling sums + NCC + per-block reduction.
// Each g_B element is loaded from global exactly once (3 packed loads = 10 B);
// the subtract-tap is served from a per-thread smem ring (no syncs needed:
// ring[sl][x] is written and read only by thread x).
// grid = (BATCH*DIM [b,y lines], NCHUNK [z chunks]); block = 192 (x).
// ---------------------------------------------------------------------------
__global__ __launch_bounds__(DIM) void k_pass3() {
    __shared__ unsigned r01[WIN][DIM];
    __shared__ unsigned r23[WIN][DIM];
    __shared__ __half   r4 [WIN][DIM];
    __shared__ float    red[DIM];

    const int by = blockIdx.x;                // b*DIM + y
    const int b  = by / DIM;
    const int y  = by % DIM;
    const int z0 = blockIdx.y * CHUNK;
    const int x  = threadIdx.x;
    const int base = b * VOL + y * DIM + x;

    float s0 = 0.f, s1 = 0.f, s2 = 0.f, s3 = 0.f, s4 = 0.f;

    auto load_row = [&](int r) {
        const int id = base + r * PLANE;
        const unsigned u01 = gB01[id];
        const unsigned u23 = gB23[id];
        const __half   h4  = gB4[id];
        const int sl = r % WIN;
        r01[sl][x] = u01; r23[sl][x] = u23; r4[sl][x] = h4;
        const float2 f01 = up2(u01);
        const float2 f23 = up2(u23);
        s0 += f01.x; s1 += f01.y; s2 += f23.x; s3 += f23.y;
        s4 += __half2float(h4);
    };

    const int rlo = (z0 - RW < 0) ? 0 : (z0 - RW);
    for (int r = rlo; r <= z0 + RW; r++) load_row(r);

    float acc = 0.f;
    for (int z = z0; ; z++) {
        const float uI = s0 * INV729;
        const float uJ = s1 * INV729;
        const float I2 = s2 * INV729 - uI * uI;
        const float J2 = s3 * INV729 - uJ * uJ;
        const float IJ = s4 * INV729 - uI * uJ;
        acc += (IJ * IJ) / (I2 * J2 + EPSV);
        if (z == z0 + CHUNK - 1) break;

        const int rs = z - RW;
        if (rs >= 0) {
            const int sl = rs % WIN;
            const float2 f01 = up2(r01[sl][x]);
            const float2 f23 = up2(r23[sl][x]);
            s0 -= f01.x; s1 -= f01.y; s2 -= f23.x; s3 -= f23.y;
            s4 -= __half2float(r4[sl][x]);
        }
        const int ra = z + RW + 1;
        if (ra < DIM) load_row(ra);
    }

    // Block tree-reduce 192 partials (192 = 3 * 2^6), deterministic order.
    red[x] = acc;
    __syncthreads();
#pragma unroll
    for (int s = 96; s >= 3; s >>= 1) {
        if (x < s) red[x] += red[x + s];
        __syncthreads();
    }
    if (x == 0) {
        g_part[blockIdx.y * (BATCH * DIM) + blockIdx.x] = red[0] + red[1] + red[2];
    }
}

// ---------------------------------------------------------------------------
// Final: deterministic fixed-order sum of 1536 partials -> -mean(ncc).
// ---------------------------------------------------------------------------
__global__ void k_final(float* __restrict__ out) {
    __shared__ float red[256];
    const int t = threadIdx.x;
    float acc = 0.f;
    for (int i = t; i < BATCH * DIM * NCHUNK; i += 256) acc += g_part[i];
    red[t] = acc;
    __syncthreads();
#pragma unroll
    for (int s = 128; s > 0; s >>= 1) {
        if (t < s) red[t] += red[t + s];
        __syncthreads();
    }
    if (t == 0) out[0] = -red[0] * (1.0f / (float)NVOX);
}

extern "C" void kernel_launch(void* const* d_in, const int* in_sizes, int n_in,
                              void* d_out, int out_size) {
    const float* y_pred = (const float*)d_in[0];
    const float* y_true = (const float*)d_in[1];
    float* out = (float*)d_out;

    k_pass12<<<dim3(BATCH * DIM, NCHUNK), DIM>>>(y_pred, y_true);
    k_pass3 <<<dim3(BATCH * DIM, NCHUNK), DIM>>>();
    k_final <<<1, 256>>>(out);
}

// round 10
// speedup vs baseline: 2.1600x; 1.0045x over previous
#include <cuda_runtime.h>
#include <cuda_fp16.h>

// Problem constants
#define BATCH 2
#define DIM   192
#define PLANE (DIM*DIM)           // 36864
#define VOL   (DIM*DIM*DIM)       // 7077888
#define NVOX  (BATCH*VOL)         // 14155776
#define RW    4                   // window radius (WIN=9)
#define WIN   9
#define INV729 (1.0f/729.0f)
#define EPSV  1e-5f
#define CHUNK 48                  // y/z chunk per block (192/48 = 4 chunks)
#define NCHUNK (DIM/CHUNK)
#define TPB   96                  // 96 threads, each owns x = 2t, 2t+1
#define NBLK  (BATCH*DIM*NCHUNK)  // 1536 pass3 blocks

// Intermediates (after fused x+y pass): five pooled-sum fields packed in half.
__device__ unsigned gB01[NVOX];   // half2(s0, s1)  = (SumI, SumJ)
__device__ unsigned gB23[NVOX];   // half2(s2, s3)  = (SumI2, SumJ2)
__device__ __half   gB4 [NVOX];   // half(s4)       = SumIJ
__device__ float    g_part[NBLK]; // per-block partial ncc sums
__device__ unsigned g_done = 0;   // last-block counter (self-resetting)

__device__ __forceinline__ unsigned pk2(float a, float b) {
    __half2 h = __floats2half2_rn(a, b);
    return *reinterpret_cast<unsigned*>(&h);
}
__device__ __forceinline__ float2 up2(unsigned u) {
    __half2 h = *reinterpret_cast<__half2*>(&u);
    return __half22float2(h);
}

// ---------------------------------------------------------------------------
// Fused pass 1+2, x-coarsened x2. Each thread produces outputs (x0, x0+1).
// x-box: the pair shares taps w[0..9]; per field compute the 10-tap sum S,
// then even = S - w[9], odd = S - w[0]  (5 LDS.64 per array per row).
// y-box: register rolling sums; smem ring (packed half) of last 9 x-boxed
// rows serves the subtract-tap. Round-to-half BEFORE adding to the rolling
// sum so the later ring-subtract removes exactly what was added (no drift).
// Double-buffered input rows -> one __syncthreads per row.
// ---------------------------------------------------------------------------
__global__ __launch_bounds__(TPB, 10) void k_pass12(
    const float* __restrict__ I, const float* __restrict__ J)
{
    __shared__ unsigned r01[WIN][DIM];            // 6.9 KB (pairs adjacent)
    __shared__ unsigned r23[WIN][DIM];            // 6.9 KB
    __shared__ __half   r4 [WIN][DIM];            // 3.5 KB
    __shared__ __align__(16) float sbuf[2][2][DIM + 2*RW]; // 6.4 KB

    const int bz = blockIdx.x;                    // b*DIM + z
    const int y0 = blockIdx.y * CHUNK;
    const int t  = threadIdx.x;
    const int x0 = 2 * t;
    const int pb = bz * PLANE;

    if (t < RW) {                                 // zero pads (both parities)
#pragma unroll
        for (int p = 0; p < 2; p++) {
            sbuf[p][0][t] = 0.f;            sbuf[p][1][t] = 0.f;
            sbuf[p][0][RW + DIM + t] = 0.f; sbuf[p][1][RW + DIM + t] = 0.f;
        }
    }

    // rolling sums: even output (x0) and odd output (x0+1)
    float sE0=0.f,sE1=0.f,sE2=0.f,sE3=0.f,sE4=0.f;
    float sO0=0.f,sO1=0.f,sO2=0.f,sO3=0.f,sO4=0.f;

    auto do_row = [&](int r) {
        float* sI = sbuf[r & 1][0];
        float* sJ = sbuf[r & 1][1];
        const float2 iv = *reinterpret_cast<const float2*>(&I[pb + r*DIM + x0]);
        const float2 jv = *reinterpret_cast<const float2*>(&J[pb + r*DIM + x0]);
        *reinterpret_cast<float2*>(&sI[RW + x0]) = iv;
        *reinterpret_cast<float2*>(&sJ[RW + x0]) = jv;
        __syncthreads();

        // 10 shared taps w[0..9] = sI[x0..x0+9] via 5 float2 loads (x0 even)
        float S0=0.f,S1=0.f,S2=0.f,S3=0.f,S4=0.f;
        float u0=0.f,v0=0.f,u9=0.f,v9=0.f;
#pragma unroll
        for (int k = 0; k < 10; k += 2) {
            const float2 uu = *reinterpret_cast<const float2*>(&sI[x0 + k]);
            const float2 vv = *reinterpret_cast<const float2*>(&sJ[x0 + k]);
            if (k == 0) { u0 = uu.x; v0 = vv.x; }
            if (k == 8) { u9 = uu.y; v9 = vv.y; }
            S0 += uu.x; S1 += vv.x; S2 += uu.x*uu.x; S3 += vv.x*vv.x; S4 += uu.x*vv.x;
            S0 += uu.y; S1 += vv.y; S2 += uu.y*uu.y; S3 += vv.y*vv.y; S4 += uu.y*vv.y;
        }
        // even = 10-tap sum minus tap9; odd = minus tap0
        const unsigned e01 = pk2(S0 - u9,    S1 - v9);
        const unsigned e23 = pk2(S2 - u9*u9, S3 - v9*v9);
        const __half   e4  = __float2half_rn(S4 - u9*v9);
        const unsigned o01 = pk2(S0 - u0,    S1 - v0);
        const unsigned o23 = pk2(S2 - u0*u0, S3 - v0*v0);
        const __half   o4  = __float2half_rn(S4 - u0*v0);

        const int sl = r % WIN;
        *reinterpret_cast<uint2*>(&r01[sl][x0]) = make_uint2(e01, o01);
        *reinterpret_cast<uint2*>(&r23[sl][x0]) = make_uint2(e23, o23);
        *reinterpret_cast<__half2*>(&r4[sl][x0]) = __halves2half2(e4, o4);

        const float2 fe01 = up2(e01), fe23 = up2(e23);
        const float2 fo01 = up2(o01), fo23 = up2(o23);
        sE0 += fe01.x; sE1 += fe01.y; sE2 += fe23.x; sE3 += fe23.y; sE4 += __half2float(e4);
        sO0 += fo01.x; sO1 += fo01.y; sO2 += fo23.x; sO3 += fo23.y; sO4 += __half2float(o4);
    };

    const int rlo = (y0 - RW < 0) ? 0 : (y0 - RW);
    for (int r = rlo; r <= y0 + RW; r++) do_row(r);

    for (int y = y0; ; y++) {
        const int id = pb + y * DIM + x0;
        *reinterpret_cast<uint2*>(&gB01[id]) = make_uint2(pk2(sE0,sE1), pk2(sO0,sO1));
        *reinterpret_cast<uint2*>(&gB23[id]) = make_uint2(pk2(sE2,sE3), pk2(sO2,sO3));
        *reinterpret_cast<__half2*>(&gB4[id]) =
            __halves2half2(__float2half_rn(sE4), __float2half_rn(sO4));
        if (y == y0 + CHUNK - 1) break;

        const int rs = y - RW;                    // leaving row (exact subtract)
        if (rs >= 0) {
            const int sl = rs % WIN;
            const uint2 q01 = *reinterpret_cast<const uint2*>(&r01[sl][x0]);
            const uint2 q23 = *reinterpret_cast<const uint2*>(&r23[sl][x0]);
            const __half2 q4 = *reinterpret_cast<const __half2*>(&r4[sl][x0]);
            const float2 fe01 = up2(q01.x), fe23 = up2(q23.x);
            const float2 fo01 = up2(q01.y), fo23 = up2(q23.y);
            const float2 f4   = __half22float2(q4);
            sE0 -= fe01.x; sE1 -= fe01.y; sE2 -= fe23.x; sE3 -= fe23.y; sE4 -= f4.x;
            sO0 -= fo01.x; sO1 -= fo01.y; sO2 -= fo23.x; sO3 -= fo23.y; sO4 -= f4.y;
        }
        const int ra = y + RW + 1;                // entering row
        if (ra < DIM) do_row(ra);
    }
}

// ---------------------------------------------------------------------------
// Pass 3, x-coarsened x2: z-direction rolling sums + NCC + block reduction,
// with the grid-wide final reduction folded in (fence + atomic-counter
// last-block pattern; deterministic — partial values and the fixed t-strided
// summation order are identical on every replay; counter self-resets).
// ---------------------------------------------------------------------------
__global__ __launch_bounds__(TPB, 10) void k_pass3(float* __restrict__ out) {
    __shared__ unsigned r01[WIN][DIM];
    __shared__ unsigned r23[WIN][DIM];
    __shared__ __half   r4 [WIN][DIM];
    __shared__ float    red[TPB];
    __shared__ int      s_last;

    const int by = blockIdx.x;                    // b*DIM + y
    const int b  = by / DIM;
    const int y  = by % DIM;
    const int z0 = blockIdx.y * CHUNK;
    const int t  = threadIdx.x;
    const int x0 = 2 * t;
    const int base = b * VOL + y * DIM + x0;

    float sE0=0.f,sE1=0.f,sE2=0.f,sE3=0.f,sE4=0.f;
    float sO0=0.f,sO1=0.f,sO2=0.f,sO3=0.f,sO4=0.f;

    auto load_row = [&](int r) {
        const int id = base + r * PLANE;
        const uint2  q01 = *reinterpret_cast<const uint2*>(&gB01[id]);
        const uint2  q23 = *reinterpret_cast<const uint2*>(&gB23[id]);
        const __half2 q4 = *reinterpret_cast<const __half2*>(&gB4[id]);
        const int sl = r % WIN;
        *reinterpret_cast<uint2*>(&r01[sl][x0]) = q01;
        *reinterpret_cast<uint2*>(&r23[sl][x0]) = q23;
        *reinterpret_cast<__half2*>(&r4[sl][x0]) = q4;
        const float2 fe01 = up2(q01.x), fe23 = up2(q23.x);
        const float2 fo01 = up2(q01.y), fo23 = up2(q23.y);
        const float2 f4   = __half22float2(q4);
        sE0 += fe01.x; sE1 += fe01.y; sE2 += fe23.x; sE3 += fe23.y; sE4 += f4.x;
        sO0 += fo01.x; sO1 += fo01.y; sO2 += fo23.x; sO3 += fo23.y; sO4 += f4.y;
    };

    const int rlo = (z0 - RW < 0) ? 0 : (z0 - RW);
    for (int r = rlo; r <= z0 + RW; r++) load_row(r);

    float acc = 0.f;
    for (int z = z0; ; z++) {
        {
            const float uI = sE0 * INV729, uJ = sE1 * INV729;
            const float I2 = sE2 * INV729 - uI * uI;
            const float J2 = sE3 * INV729 - uJ * uJ;
            const float IJ = sE4 * INV729 - uI * uJ;
            acc += (IJ * IJ) / (I2 * J2 + EPSV);
        }
        {
            const float uI = sO0 * INV729, uJ = sO1 * INV729;
            const float I2 = sO2 * INV729 - uI * uI;
            const float J2 = sO3 * INV729 - uJ * uJ;
            const float IJ = sO4 * INV729 - uI * uJ;
            acc += (IJ * IJ) / (I2 * J2 + EPSV);
        }
        if (z == z0 + CHUNK - 1) break;

        const int rs = z - RW;
        if (rs >= 0) {
            const int sl = rs % WIN;
            const uint2 q01 = *reinterpret_cast<const uint2*>(&r01[sl][x0]);
            const uint2 q23 = *reinterpret_cast<const uint2*>(&r23[sl][x0]);
            const __half2 q4 = *reinterpret_cast<const __half2*>(&r4[sl][x0]);
            const float2 fe01 = up2(q01.x), fe23 = up2(q23.x);
            const float2 fo01 = up2(q01.y), fo23 = up2(q23.y);
            const float2 f4   = __half22float2(q4);
            sE0 -= fe01.x; sE1 -= fe01.y; sE2 -= fe23.x; sE3 -= fe23.y; sE4 -= f4.x;
            sO0 -= fo01.x; sO1 -= fo01.y; sO2 -= fo23.x; sO3 -= fo23.y; sO4 -= f4.y;
        }
        const int ra = z + RW + 1;
        if (ra < DIM) load_row(ra);
    }

    // Block tree-reduce 96 partials (96 = 3 * 2^5), deterministic order.
    red[t] = acc;
    __syncthreads();
#pragma unroll
    for (int s = 48; s >= 3; s >>= 1) {
        if (t < s) red[t] += red[t + s];
        __syncthreads();
    }
    if (t == 0) {
        g_part[blockIdx.y * (BATCH * DIM) + blockIdx.x] = red[0] + red[1] + red[2];
        __threadfence();
        const unsigned v = atomicAdd(&g_done, 1u);
        s_last = (v == NBLK - 1);
    }
    __syncthreads();

    if (s_last) {                                 // exactly one block runs this
        float a = 0.f;
        for (int i = t; i < NBLK; i += TPB) a += g_part[i];
        red[t] = a;
        __syncthreads();
#pragma unroll
        for (int s = 48; s >= 3; s >>= 1) {
            if (t < s) red[t] += red[t + s];
            __syncthreads();
        }
        if (t == 0) {
            out[0] = -(red[0] + red[1] + red[2]) * (1.0f / (float)NVOX);
            g_done = 0;                           // reset for next graph replay
        }
    }
}

extern "C" void kernel_launch(void* const* d_in, const int* in_sizes, int n_in,
                              void* d_out, int out_size) {
    const float* y_pred = (const float*)d_in[0];
    const float* y_true = (const float*)d_in[1];
    float* out = (float*)d_out;

    k_pass12<<<dim3(BATCH * DIM, NCHUNK), TPB>>>(y_pred, y_true);
    k_pass3 <<<dim3(BATCH * DIM, NCHUNK), TPB>>>(out);
}

// round 12
// speedup vs baseline: 2.3014x; 1.0654x over previous
#include <cuda_runtime.h>
#include <cuda_fp16.h>

// Problem constants
#define BATCH 2
#define DIM   192
#define PLANE (DIM*DIM)           // 36864
#define VOL   (DIM*DIM*DIM)       // 7077888
#define NVOX  (BATCH*VOL)         // 14155776
#define RW    4                   // window radius (WIN=9)
#define WIN   9
#define INV729 (1.0f/729.0f)
#define EPSV  1e-5f
#define CHUNK 48                  // y/z chunk per block (192/48 = 4 chunks)
#define NCHUNK (DIM/CHUNK)
#define TPB12 96                  // pass12: 96 threads, each owns x = 2t, 2t+1
#define TPB3  192                 // pass3: 192 threads, one x each (latency-bound
                                  // kernel -> maximize warps in flight)
#define NBLK  (BATCH*DIM*NCHUNK)  // 1536 pass3 blocks

// Intermediates (after fused x+y pass): five pooled-sum fields packed in half.
__device__ unsigned gB01[NVOX];   // half2(s0, s1)  = (SumI, SumJ)
__device__ unsigned gB23[NVOX];   // half2(s2, s3)  = (SumI2, SumJ2)
__device__ __half   gB4 [NVOX];   // half(s4)       = SumIJ
__device__ float    g_part[NBLK]; // per-block partial ncc sums
__device__ unsigned g_done = 0;   // last-block counter (self-resetting)

__device__ __forceinline__ unsigned pk2(float a, float b) {
    __half2 h = __floats2half2_rn(a, b);
    return *reinterpret_cast<unsigned*>(&h);
}
__device__ __forceinline__ float2 up2(unsigned u) {
    __half2 h = *reinterpret_cast<__half2*>(&u);
    return __half22float2(h);
}

// ---------------------------------------------------------------------------
// Fused pass 1+2, x-coarsened x2 (issue-bound kernel -> fewer instructions
// per output). Each thread produces outputs (x0, x0+1).
// x-box: the pair shares taps w[0..9]; per field compute the 10-tap sum S,
// then even = S - w[9], odd = S - w[0]  (5 LDS.64 per array per row).
// y-box: register rolling sums; smem ring (packed half) of last 9 x-boxed
// rows serves the subtract-tap. Round-to-half BEFORE adding to the rolling
// sum so the later ring-subtract removes exactly what was added (no drift).
// Double-buffered input rows -> one __syncthreads per row.
// ---------------------------------------------------------------------------
__global__ __launch_bounds__(TPB12, 10) void k_pass12(
    const float* __restrict__ I, const float* __restrict__ J)
{
    __shared__ unsigned r01[WIN][DIM];            // 6.9 KB (pairs adjacent)
    __shared__ unsigned r23[WIN][DIM];            // 6.9 KB
    __shared__ __half   r4 [WIN][DIM];            // 3.5 KB
    __shared__ __align__(16) float sbuf[2][2][DIM + 2*RW]; // 6.4 KB

    const int bz = blockIdx.x;                    // b*DIM + z
    const int y0 = blockIdx.y * CHUNK;
    const int t  = threadIdx.x;
    const int x0 = 2 * t;
    const int pb = bz * PLANE;

    if (t < RW) {                                 // zero pads (both parities)
#pragma unroll
        for (int p = 0; p < 2; p++) {
            sbuf[p][0][t] = 0.f;            sbuf[p][1][t] = 0.f;
            sbuf[p][0][RW + DIM + t] = 0.f; sbuf[p][1][RW + DIM + t] = 0.f;
        }
    }

    // rolling sums: even output (x0) and odd output (x0+1)
    float sE0=0.f,sE1=0.f,sE2=0.f,sE3=0.f,sE4=0.f;
    float sO0=0.f,sO1=0.f,sO2=0.f,sO3=0.f,sO4=0.f;

    auto do_row = [&](int r) {
        float* sI = sbuf[r & 1][0];
        float* sJ = sbuf[r & 1][1];
        const float2 iv = *reinterpret_cast<const float2*>(&I[pb + r*DIM + x0]);
        const float2 jv = *reinterpret_cast<const float2*>(&J[pb + r*DIM + x0]);
        *reinterpret_cast<float2*>(&sI[RW + x0]) = iv;
        *reinterpret_cast<float2*>(&sJ[RW + x0]) = jv;
        __syncthreads();

        // 10 shared taps w[0..9] = sI[x0..x0+9] via 5 float2 loads (x0 even)
        float S0=0.f,S1=0.f,S2=0.f,S3=0.f,S4=0.f;
        float u0=0.f,v0=0.f,u9=0.f,v9=0.f;
#pragma unroll
        for (int k = 0; k < 10; k += 2) {
            const float2 uu = *reinterpret_cast<const float2*>(&sI[x0 + k]);
            const float2 vv = *reinterpret_cast<const float2*>(&sJ[x0 + k]);
            if (k == 0) { u0 = uu.x; v0 = vv.x; }
            if (k == 8) { u9 = uu.y; v9 = vv.y; }
            S0 += uu.x; S1 += vv.x; S2 += uu.x*uu.x; S3 += vv.x*vv.x; S4 += uu.x*vv.x;
            S0 += uu.y; S1 += vv.y; S2 += uu.y*uu.y; S3 += vv.y*vv.y; S4 += uu.y*vv.y;
        }
        // even = 10-tap sum minus tap9; odd = minus tap0
        const unsigned e01 = pk2(S0 - u9,    S1 - v9);
        const unsigned e23 = pk2(S2 - u9*u9, S3 - v9*v9);
        const __half   e4  = __float2half_rn(S4 - u9*v9);
        const unsigned o01 = pk2(S0 - u0,    S1 - v0);
        const unsigned o23 = pk2(S2 - u0*u0, S3 - v0*v0);
        const __half   o4  = __float2half_rn(S4 - u0*v0);

        const int sl = r % WIN;
        *reinterpret_cast<uint2*>(&r01[sl][x0]) = make_uint2(e01, o01);
        *reinterpret_cast<uint2*>(&r23[sl][x0]) = make_uint2(e23, o23);
        *reinterpret_cast<__half2*>(&r4[sl][x0]) = __halves2half2(e4, o4);

        const float2 fe01 = up2(e01), fe23 = up2(e23);
        const float2 fo01 = up2(o01), fo23 = up2(o23);
        sE0 += fe01.x; sE1 += fe01.y; sE2 += fe23.x; sE3 += fe23.y; sE4 += __half2float(e4);
        sO0 += fo01.x; sO1 += fo01.y; sO2 += fo23.x; sO3 += fo23.y; sO4 += __half2float(o4);
    };

    const int rlo = (y0 - RW < 0) ? 0 : (y0 - RW);
    for (int r = rlo; r <= y0 + RW; r++) do_row(r);

    for (int y = y0; ; y++) {
        const int id = pb + y * DIM + x0;
        *reinterpret_cast<uint2*>(&gB01[id]) = make_uint2(pk2(sE0,sE1), pk2(sO0,sO1));
        *reinterpret_cast<uint2*>(&gB23[id]) = make_uint2(pk2(sE2,sE3), pk2(sO2,sO3));
        *reinterpret_cast<__half2*>(&gB4[id]) =
            __halves2half2(__float2half_rn(sE4), __float2half_rn(sO4));
        if (y == y0 + CHUNK - 1) break;

        const int rs = y - RW;                    // leaving row (exact subtract)
        if (rs >= 0) {
            const int sl = rs % WIN;
            const uint2 q01 = *reinterpret_cast<const uint2*>(&r01[sl][x0]);
            const uint2 q23 = *reinterpret_cast<const uint2*>(&r23[sl][x0]);
            const __half2 q4 = *reinterpret_cast<const __half2*>(&r4[sl][x0]);
            const float2 fe01 = up2(q01.x), fe23 = up2(q23.x);
            const float2 fo01 = up2(q01.y), fo23 = up2(q23.y);
            const float2 f4   = __half22float2(q4);
            sE0 -= fe01.x; sE1 -= fe01.y; sE2 -= fe23.x; sE3 -= fe23.y; sE4 -= f4.x;
            sO0 -= fo01.x; sO1 -= fo01.y; sO2 -= fo23.x; sO3 -= fo23.y; sO4 -= f4.y;
        }
        const int ra = y + RW + 1;                // entering row
        if (ra < DIM) do_row(ra);
    }
}

// ---------------------------------------------------------------------------
// Pass 3 (latency-bound -> 192 threads, one x each, max warps in flight):
// z-direction rolling sums + NCC + block reduction, grid-wide final folded in
// (fence + atomic-counter last-block pattern; deterministic on every replay;
// counter self-resets). Entering-row loads are issued BEFORE the subtract/ncc
// math so LDG latency overlaps the FMA work.
// ---------------------------------------------------------------------------
__global__ __launch_bounds__(TPB3) void k_pass3(float* __restrict__ out) {
    __shared__ unsigned r01[WIN][DIM];
    __shared__ unsigned r23[WIN][DIM];
    __shared__ __half   r4 [WIN][DIM];
    __shared__ float    red[TPB3];
    __shared__ int      s_last;

    const int by = blockIdx.x;                    // b*DIM + y
    const int b  = by / DIM;
    const int y  = by % DIM;
    const int z0 = blockIdx.y * CHUNK;
    const int x  = threadIdx.x;
    const int base = b * VOL + y * DIM + x;

    float s0=0.f,s1=0.f,s2=0.f,s3=0.f,s4=0.f;

    auto push_row = [&](unsigned u01, unsigned u23, __half h4, int r) {
        const int sl = r % WIN;
        r01[sl][x] = u01; r23[sl][x] = u23; r4[sl][x] = h4;
        const float2 f01 = up2(u01), f23 = up2(u23);
        s0 += f01.x; s1 += f01.y; s2 += f23.x; s3 += f23.y;
        s4 += __half2float(h4);
    };

    const int rlo = (z0 - RW < 0) ? 0 : (z0 - RW);
    for (int r = rlo; r <= z0 + RW; r++) {
        const int id = base + r * PLANE;
        push_row(gB01[id], gB23[id], gB4[id], r);
    }

    float acc = 0.f;
    for (int z = z0; ; z++) {
        // Issue next-row loads first: overlap ~600cyc LDG with the math below.
        const int ra = z + RW + 1;
        const bool have_a = (ra < DIM) && (z != z0 + CHUNK - 1);
        unsigned u01 = 0, u23 = 0; __half h4 = __float2half_rn(0.f);
        if (have_a) {
            const int id = base + ra * PLANE;
            u01 = gB01[id]; u23 = gB23[id]; h4 = gB4[id];
        }

        const float uI = s0 * INV729, uJ = s1 * INV729;
        const float I2 = s2 * INV729 - uI * uI;
        const float J2 = s3 * INV729 - uJ * uJ;
        const float IJ = s4 * INV729 - uI * uJ;
        acc += (IJ * IJ) / (I2 * J2 + EPSV);
        if (z == z0 + CHUNK - 1) break;

        const int rs = z - RW;
        if (rs >= 0) {
            const int sl = rs % WIN;
            const float2 f01 = up2(r01[sl][x]);
            const float2 f23 = up2(r23[sl][x]);
            s0 -= f01.x; s1 -= f01.y; s2 -= f23.x; s3 -= f23.y;
            s4 -= __half2float(r4[sl][x]);
        }
        if (have_a) push_row(u01, u23, h4, ra);
    }

    // Block tree-reduce 192 partials (192 = 3 * 2^6), deterministic order.
    red[x] = acc;
    __syncthreads();
#pragma unroll
    for (int s = 96; s >= 3; s >>= 1) {
        if (x < s) red[x] += red[x + s];
        __syncthreads();
    }
    if (x == 0) {
        g_part[blockIdx.y * (BATCH * DIM) + blockIdx.x] = red[0] + red[1] + red[2];
        __threadfence();
        const unsigned v = atomicAdd(&g_done, 1u);
        s_last = (v == NBLK - 1);
    }
    __syncthreads();

    if (s_last) {                                 // exactly one block runs this
        float a = 0.f;
        for (int i = x; i < NBLK; i += TPB3) a += g_part[i];
        red[x] = a;
        __syncthreads();
#pragma unroll
        for (int s = 96; s >= 3; s >>= 1) {
            if (x < s) red[x] += red[x + s];
            __syncthreads();
        }
        if (x == 0) {
            out[0] = -(red[0] + red[1] + red[2]) * (1.0f / (float)NVOX);
            g_done = 0;                           // reset for next graph replay
        }
    }
}

extern "C" void kernel_launch(void* const* d_in, const int* in_sizes, int n_in,
                              void* d_out, int out_size) {
    const float* y_pred = (const float*)d_in[0];
    const float* y_true = (const float*)d_in[1];
    float* out = (float*)d_out;

    k_pass12<<<dim3(BATCH * DIM, NCHUNK), TPB12>>>(y_pred, y_true);
    k_pass3 <<<dim3(BATCH * DIM, NCHUNK), TPB3>>>(out);
}

// round 13
// speedup vs baseline: 2.4263x; 1.0543x over previous
#include <cuda_runtime.h>
#include <cuda_fp16.h>

// Problem constants
#define BATCH 2
#define DIM   192
#define PLANE (DIM*DIM)           // 36864
#define VOL   (DIM*DIM*DIM)       // 7077888
#define NVOX  (BATCH*VOL)         // 14155776
#define RW    4                   // window radius (WIN=9)
#define WIN   9
#define INV729 (1.0f/729.0f)
#define EPSV  1e-5f
#define CHUNK 48                  // y/z chunk per block (192/48 = 4 chunks)
#define NCHUNK (DIM/CHUNK)
#define TPB12 96                  // pass12: 96 threads, each owns x = 2t, 2t+1
#define TPB3  192                 // pass3: 192 threads, one x each
#define NBLK  (BATCH*DIM*NCHUNK)  // 1536 pass3 blocks

// Intermediates (after fused x+y pass): five pooled-sum fields packed in half.
__device__ unsigned gB01[NVOX];   // half2(s0, s1)  = (SumI, SumJ)
__device__ unsigned gB23[NVOX];   // half2(s2, s3)  = (SumI2, SumJ2)
__device__ __half   gB4 [NVOX];   // half(s4)       = SumIJ
__device__ float    g_part[NBLK]; // per-block partial ncc sums
__device__ unsigned g_done = 0;   // last-block counter (self-resetting)

__device__ __forceinline__ unsigned h2u(__half2 h) {
    return *reinterpret_cast<unsigned*>(&h);
}
__device__ __forceinline__ __half2 u2h(unsigned u) {
    return *reinterpret_cast<__half2*>(&u);
}

// ---------------------------------------------------------------------------
// Fused pass 1+2, x-coarsened x2. x-box in fp32 (smem row, shared 10-tap sum
// + endpoint corrections); y-box rolling sums kept in PACKED HALF2 registers
// (HADD2/HSUB2 — the ring stores the identical half2 values, so add/subtract
// operate on the same quantities; residual error is bounded half-arithmetic
// rounding, no fp32<->fp16 conversion plumbing in the rolling path).
// Double-buffered input rows -> one __syncthreads per row.
// ---------------------------------------------------------------------------
__global__ __launch_bounds__(TPB12, 9) void k_pass12(
    const float* __restrict__ I, const float* __restrict__ J)
{
    __shared__ unsigned r01[WIN][DIM];            // 6.9 KB (E/O pairs adjacent)
    __shared__ unsigned r23[WIN][DIM];            // 6.9 KB
    __shared__ __half   r4 [WIN][DIM];            // 3.5 KB (half2 at even x)
    __shared__ __align__(16) float sbuf[2][2][DIM + 2*RW]; // 6.4 KB

    const int bz = blockIdx.x;                    // b*DIM + z
    const int y0 = blockIdx.y * CHUNK;
    const int t  = threadIdx.x;
    const int x0 = 2 * t;
    const int pb = bz * PLANE;

    if (t < RW) {                                 // zero pads (both parities)
#pragma unroll
        for (int p = 0; p < 2; p++) {
            sbuf[p][0][t] = 0.f;            sbuf[p][1][t] = 0.f;
            sbuf[p][0][RW + DIM + t] = 0.f; sbuf[p][1][RW + DIM + t] = 0.f;
        }
    }

    // rolling sums, packed: E=(x0), O=(x0+1); s4EO = (E4, O4)
    const __half2 hz = __floats2half2_rn(0.f, 0.f);
    __half2 sE01 = hz, sE23 = hz, sO01 = hz, sO23 = hz, s4EO = hz;

    auto do_row = [&](int r) {
        float* sI = sbuf[r & 1][0];
        float* sJ = sbuf[r & 1][1];
        const float2 iv = *reinterpret_cast<const float2*>(&I[pb + r*DIM + x0]);
        const float2 jv = *reinterpret_cast<const float2*>(&J[pb + r*DIM + x0]);
        *reinterpret_cast<float2*>(&sI[RW + x0]) = iv;
        *reinterpret_cast<float2*>(&sJ[RW + x0]) = jv;
        __syncthreads();

        // 10 shared taps w[0..9] = sI[x0..x0+9] via 5 float2 loads (x0 even)
        float S0=0.f,S1=0.f,S2=0.f,S3=0.f,S4=0.f;
        float u0=0.f,v0=0.f,u9=0.f,v9=0.f;
#pragma unroll
        for (int k = 0; k < 10; k += 2) {
            const float2 uu = *reinterpret_cast<const float2*>(&sI[x0 + k]);
            const float2 vv = *reinterpret_cast<const float2*>(&sJ[x0 + k]);
            if (k == 0) { u0 = uu.x; v0 = vv.x; }
            if (k == 8) { u9 = uu.y; v9 = vv.y; }
            S0 += uu.x; S1 += vv.x; S2 += uu.x*uu.x; S3 += vv.x*vv.x; S4 += uu.x*vv.x;
            S0 += uu.y; S1 += vv.y; S2 += uu.y*uu.y; S3 += vv.y*vv.y; S4 += uu.y*vv.y;
        }
        // even = 10-tap sum minus tap9; odd = minus tap0. Pack once.
        const __half2 e01 = __floats2half2_rn(S0 - u9,    S1 - v9);
        const __half2 e23 = __floats2half2_rn(S2 - u9*u9, S3 - v9*v9);
        const __half2 o01 = __floats2half2_rn(S0 - u0,    S1 - v0);
        const __half2 o23 = __floats2half2_rn(S2 - u0*u0, S3 - v0*v0);
        const __half2 eo4 = __floats2half2_rn(S4 - u9*v9, S4 - u0*v0);

        const int sl = r % WIN;
        *reinterpret_cast<uint2*>(&r01[sl][x0]) = make_uint2(h2u(e01), h2u(o01));
        *reinterpret_cast<uint2*>(&r23[sl][x0]) = make_uint2(h2u(e23), h2u(o23));
        *reinterpret_cast<__half2*>(&r4[sl][x0]) = eo4;

        sE01 = __hadd2(sE01, e01); sE23 = __hadd2(sE23, e23);
        sO01 = __hadd2(sO01, o01); sO23 = __hadd2(sO23, o23);
        s4EO = __hadd2(s4EO, eo4);
    };

    const int rlo = (y0 - RW < 0) ? 0 : (y0 - RW);
    for (int r = rlo; r <= y0 + RW; r++) do_row(r);

    for (int y = y0; ; y++) {
        const int id = pb + y * DIM + x0;
        *reinterpret_cast<uint2*>(&gB01[id]) = make_uint2(h2u(sE01), h2u(sO01));
        *reinterpret_cast<uint2*>(&gB23[id]) = make_uint2(h2u(sE23), h2u(sO23));
        *reinterpret_cast<__half2*>(&gB4[id]) = s4EO;
        if (y == y0 + CHUNK - 1) break;

        const int rs = y - RW;                    // leaving row
        if (rs >= 0) {
            const int sl = rs % WIN;
            const uint2 q01 = *reinterpret_cast<const uint2*>(&r01[sl][x0]);
            const uint2 q23 = *reinterpret_cast<const uint2*>(&r23[sl][x0]);
            const __half2 q4 = *reinterpret_cast<const __half2*>(&r4[sl][x0]);
            sE01 = __hsub2(sE01, u2h(q01.x)); sO01 = __hsub2(sO01, u2h(q01.y));
            sE23 = __hsub2(sE23, u2h(q23.x)); sO23 = __hsub2(sO23, u2h(q23.y));
            s4EO = __hsub2(s4EO, q4);
        }
        const int ra = y + RW + 1;                // entering row
        if (ra < DIM) do_row(ra);
    }
}

// ---------------------------------------------------------------------------
// Pass 3 (latency/issue-bound -> 192 threads, one x each). z-rolling sums in
// packed half2 registers; unpack to fp32 only at the ncc evaluation.
// Entering-row loads issued BEFORE the math to overlap LDG latency.
// Grid-wide final reduction folded in (fence + atomic counter, deterministic,
// self-resetting).
// ---------------------------------------------------------------------------
__global__ __launch_bounds__(TPB3) void k_pass3(float* __restrict__ out) {
    __shared__ unsigned r01[WIN][DIM];
    __shared__ unsigned r23[WIN][DIM];
    __shared__ __half   r4 [WIN][DIM];
    __shared__ float    red[TPB3];
    __shared__ int      s_last;

    const int by = blockIdx.x;                    // b*DIM + y
    const int b  = by / DIM;
    const int y  = by % DIM;
    const int z0 = blockIdx.y * CHUNK;
    const int x  = threadIdx.x;
    const int base = b * VOL + y * DIM + x;

    const __half2 hz = __floats2half2_rn(0.f, 0.f);
    __half2 s01 = hz, s23 = hz;
    __half  s4  = __float2half_rn(0.f);

    auto push_row = [&](unsigned u01, unsigned u23, __half h4, int r) {
        const int sl = r % WIN;
        r01[sl][x] = u01; r23[sl][x] = u23; r4[sl][x] = h4;
        s01 = __hadd2(s01, u2h(u01));
        s23 = __hadd2(s23, u2h(u23));
        s4  = __hadd(s4, h4);
    };

    const int rlo = (z0 - RW < 0) ? 0 : (z0 - RW);
    for (int r = rlo; r <= z0 + RW; r++) {
        const int id = base + r * PLANE;
        push_row(gB01[id], gB23[id], gB4[id], r);
    }

    float acc = 0.f;
    for (int z = z0; ; z++) {
        // Issue next-row loads first: overlap LDG latency with math below.
        const int ra = z + RW + 1;
        const bool have_a = (ra < DIM) && (z != z0 + CHUNK - 1);
        unsigned u01 = 0, u23 = 0; __half h4 = __float2half_rn(0.f);
        if (have_a) {
            const int id = base + ra * PLANE;
            u01 = gB01[id]; u23 = gB23[id]; h4 = gB4[id];
        }

        const float2 f01 = __half22float2(s01);
        const float2 f23 = __half22float2(s23);
        const float  f4  = __half2float(s4);
        const float uI = f01.x * INV729, uJ = f01.y * INV729;
        const float I2 = f23.x * INV729 - uI * uI;
        const float J2 = f23.y * INV729 - uJ * uJ;
        const float IJ = f4   * INV729 - uI * uJ;
        acc += (IJ * IJ) / (I2 * J2 + EPSV);
        if (z == z0 + CHUNK - 1) break;

        const int rs = z - RW;
        if (rs >= 0) {
            const int sl = rs % WIN;
            s01 = __hsub2(s01, u2h(r01[sl][x]));
            s23 = __hsub2(s23, u2h(r23[sl][x]));
            s4  = __hsub(s4, r4[sl][x]);
        }
        if (have_a) push_row(u01, u23, h4, ra);
    }

    // Block tree-reduce 192 partials (192 = 3 * 2^6), deterministic order.
    red[x] = acc;
    __syncthreads();
#pragma unroll
    for (int s = 96; s >= 3; s >>= 1) {
        if (x < s) red[x] += red[x + s];
        __syncthreads();
    }
    if (x == 0) {
        g_part[blockIdx.y * (BATCH * DIM) + blockIdx.x] = red[0] + red[1] + red[2];
        __threadfence();
        const unsigned v = atomicAdd(&g_done, 1u);
        s_last = (v == NBLK - 1);
    }
    __syncthreads();

    if (s_last) {                                 // exactly one block runs this
        float a = 0.f;
        for (int i = x; i < NBLK; i += TPB3) a += g_part[i];
        red[x] = a;
        __syncthreads();
#pragma unroll
        for (int s = 96; s >= 3; s >>= 1) {
            if (x < s) red[x] += red[x + s];
            __syncthreads();
        }
        if (x == 0) {
            out[0] = -(red[0] + red[1] + red[2]) * (1.0f / (float)NVOX);
            g_done = 0;                           // reset for next graph replay
        }
    }
}

extern "C" void kernel_launch(void* const* d_in, const int* in_sizes, int n_in,
                              void* d_out, int out_size) {
    const float* y_pred = (const float*)d_in[0];
    const float* y_true = (const float*)d_in[1];
    float* out = (float*)d_out;

    k_pass12<<<dim3(BATCH * DIM, NCHUNK), TPB12>>>(y_pred, y_true);
    k_pass3 <<<dim3(BATCH * DIM, NCHUNK), TPB3>>>(out);
}